// round 15
// baseline (speedup 1.0000x reference)
#include <cuda_runtime.h>
#include <cstdint>

#define N_NODES 100000
#define N_EDGES 3200000
#define F_IN    512
#define HID     16
#define N_CLASSES 40
#define CAP     128   // per-node in-edge bucket capacity

#define WARPS_PB 8
#define N_TILES  6250     // N_NODES / 16 (exact)
#define GB_GEMM  782      // ceil(6250 / 8); also 782*4096 >= N_EDGES
#define E_PER_BLK 4096    // 256 threads * 16 kc

// dynamic smem (floats): W1 interleaved [512][8] float2 = 8192; per-warp x tile [16][36]
#define SMEM_FLOATS (8192 + WARPS_PB * 576)   // 12800 floats = 51200 B
#define SMEM_BYTES  (SMEM_FLOATS * 4)

// Scratch (device globals: allocation-free)
__device__ float g_hg[N_NODES * HID];      // hg = relu(x@W1^T+b1)@Wg^T (no dinv)
__device__ float g_hs[N_NODES * HID];      // hs = hg * rsqrt(deg)
__device__ int   g_cnt[N_NODES];
__device__ int   g_slots[N_NODES * CAP];
__device__ int   g_is64;

__device__ __forceinline__ unsigned totf(float x) {
    unsigned r;
    asm("cvt.rna.tf32.f32 %0, %1;" : "=r"(r) : "f"(x));
    return r;
}
__device__ __forceinline__ void mma_tf32(float* d, const unsigned* a, unsigned b0, unsigned b1) {
    asm volatile(
        "mma.sync.aligned.m16n8k8.row.col.f32.tf32.tf32.f32 "
        "{%0,%1,%2,%3}, {%4,%5,%6,%7}, {%8,%9}, {%0,%1,%2,%3};"
        : "+f"(d[0]), "+f"(d[1]), "+f"(d[2]), "+f"(d[3])
        : "r"(a[0]), "r"(a[1]), "r"(a[2]), "r"(a[3]), "r"(b0), "r"(b1));
}

// ---------- prep: zero counters + dtype detect ----------
__global__ __launch_bounds__(256) void k_prep(const void* e) {
    int i = blockIdx.x * 256 + threadIdx.x;
    if (i < N_NODES) g_cnt[i] = 0;
    if (blockIdx.x == 0 && threadIdx.x < 32) {
        const long long* p = (const long long*)e;
        long long v = p[(long long)threadIdx.x * (N_EDGES / 32)];   // max 24.8MB: in-bounds
        int ok = (v >= 0 && v < N_NODES) ? 1 : 0;
        unsigned m = __ballot_sync(0xFFFFFFFFu, ok);
        if (threadIdx.x == 0) g_is64 = (m == 0xFFFFFFFFu) ? 1 : 0;
    }
}

// ---------- fused GEMM + CSR-fill ----------
// Per k-chunk (16 chunks of 32 k): each thread also claims one edge slot.
// ATOM return latency hides under the chunk's MMA/LDS body (store deferred one
// iteration). LTS-atomic work and DRAM/tensor work run concurrently in-warp.
__global__ __launch_bounds__(256) void k_gemm_fill(
    const float4* __restrict__ x4,
    const float* __restrict__ W1,
    const float* __restrict__ b1,
    const float* __restrict__ Wg,
    const void* __restrict__ e)
{
    extern __shared__ float sm[];
    float2* w1i = (float2*)sm;

    int tid = threadIdx.x;
    for (int idx = tid; idx < 4096; idx += 256) {
        int k = idx >> 3, g = idx & 7;
        float2 v;
        v.x = __uint_as_float(totf(W1[g * F_IN + k]));
        v.y = __uint_as_float(totf(W1[(g + 8) * F_IN + k]));
        w1i[idx] = v;
    }
    __syncthreads();

    int wid = tid >> 5, lane = tid & 31;
    int gid = lane >> 2, t4 = lane & 3;
    int tile = blockIdx.x * WARPS_PB + wid;
    bool tv = tile < N_TILES;
    int base = tv ? tile * 16 : 0;

    float* xw = sm + 8192 + wid * 576;   // [16][36]
    float* hw = xw;                      // h1 tile [16][20] aliased after mainloop

    // Wg fragments (register-resident)
    unsigned wgb[2][2][2];
    #pragma unroll
    for (int s = 0; s < 2; s++)
        #pragma unroll
        for (int h = 0; h < 2; h++) {
            wgb[s][h][0] = totf(__ldg(&Wg[(gid + 8 * h) * HID + t4 + 8 * s]));
            wgb[s][h][1] = totf(__ldg(&Wg[(gid + 8 * h) * HID + t4 + 4 + 8 * s]));
        }
    float bb0 = __ldg(&b1[2 * t4]);
    float bb1 = __ldg(&b1[2 * t4 + 1]);
    float bb2 = __ldg(&b1[2 * t4 + 8]);
    float bb3 = __ldg(&b1[2 * t4 + 9]);

    float d0[4] = {0.f, 0.f, 0.f, 0.f};
    float d1[4] = {0.f, 0.f, 0.f, 0.f};

    int c8 = lane & 7;       // float4 col 0..7 in 32-k chunk
    int r4 = lane >> 3;      // row group 0..3

    int is64 = g_is64;
    int ebase = blockIdx.x * E_PER_BLK + tid;

    // pending edge store (deferred one kc for ATOM latency hiding)
    int pend_d = 0, pend_s = 0, pend_pos = CAP;

    // preload x chunk 0 (4 LDG.128/lane)
    float4 pf[4];
    #pragma unroll
    for (int p = 0; p < 4; p++)
        pf[p] = __ldg(x4 + (long long)(base + 4 * p + r4) * (F_IN / 4) + c8);

    #pragma unroll 1
    for (int kc = 0; kc < 16; kc++) {
        // --- edge phase: claim slot for edge (ebase + kc*256), store previous
        int ei = ebase + kc * 256;
        int es = 0, ed = 0, pos = CAP;
        bool ev = ei < N_EDGES;
        if (ev) {
            if (is64) {
                es = (int)((const long long*)e)[ei];
                ed = (int)((const long long*)e)[(long long)N_EDGES + ei];
            } else {
                es = ((const int*)e)[ei];
                ed = ((const int*)e)[N_EDGES + ei];
            }
            pos = atomicAdd(&g_cnt[ed], 1);
        }
        if (pend_pos < CAP) g_slots[pend_d * CAP + pend_pos] = pend_s;
        pend_d = ed; pend_s = es; pend_pos = ev ? pos : CAP;

        // --- x stage: store current prefetch to smem, start next chunk's loads
        #pragma unroll
        for (int p = 0; p < 4; p++) {
            float4 cv;
            cv.x = __uint_as_float(totf(pf[p].x));
            cv.y = __uint_as_float(totf(pf[p].y));
            cv.z = __uint_as_float(totf(pf[p].z));
            cv.w = __uint_as_float(totf(pf[p].w));
            ((float4*)(xw + (4 * p + r4) * 36))[c8] = cv;
        }
        __syncwarp();
        if (kc < 15) {
            #pragma unroll
            for (int p = 0; p < 4; p++)
                pf[p] = __ldg(x4 + (long long)(base + 4 * p + r4) * (F_IN / 4) + (kc + 1) * 8 + c8);
        }

        // --- MMA over this 32-k chunk
        #pragma unroll
        for (int s = 0; s < 4; s++) {
            int kl = s * 8;
            unsigned a[4];
            a[0] = __float_as_uint(xw[gid * 36 + kl + t4]);
            a[1] = __float_as_uint(xw[(gid + 8) * 36 + kl + t4]);
            a[2] = __float_as_uint(xw[gid * 36 + kl + t4 + 4]);
            a[3] = __float_as_uint(xw[(gid + 8) * 36 + kl + t4 + 4]);
            int kg = kc * 32 + kl;
            float2 bA = w1i[(kg + t4) * 8 + gid];
            float2 bB = w1i[(kg + t4 + 4) * 8 + gid];
            mma_tf32(d0, a, __float_as_uint(bA.x), __float_as_uint(bB.x));
            mma_tf32(d1, a, __float_as_uint(bA.y), __float_as_uint(bB.y));
        }
        __syncwarp();
    }

    // flush last pending edge
    if (pend_pos < CAP) g_slots[pend_d * CAP + pend_pos] = pend_s;

    if (!tv) return;

    // bias + relu -> h1 tile [16][20] (aliased)
    {
        float v;
        v = d0[0] + bb0; hw[gid * 20 + 2 * t4]           = v > 0.f ? v : 0.f;
        v = d0[1] + bb1; hw[gid * 20 + 2 * t4 + 1]       = v > 0.f ? v : 0.f;
        v = d0[2] + bb0; hw[(gid + 8) * 20 + 2 * t4]     = v > 0.f ? v : 0.f;
        v = d0[3] + bb1; hw[(gid + 8) * 20 + 2 * t4 + 1] = v > 0.f ? v : 0.f;
        v = d1[0] + bb2; hw[gid * 20 + 2 * t4 + 8]       = v > 0.f ? v : 0.f;
        v = d1[1] + bb3; hw[gid * 20 + 2 * t4 + 9]       = v > 0.f ? v : 0.f;
        v = d1[2] + bb2; hw[(gid + 8) * 20 + 2 * t4 + 8] = v > 0.f ? v : 0.f;
        v = d1[3] + bb3; hw[(gid + 8) * 20 + 2 * t4 + 9] = v > 0.f ? v : 0.f;
    }
    __syncwarp();

    // hg = h1 @ Wg^T (Wg frags resident)
    float e0[4] = {0.f, 0.f, 0.f, 0.f};
    float e1[4] = {0.f, 0.f, 0.f, 0.f};
    #pragma unroll
    for (int s = 0; s < 2; s++) {
        int kl = s * 8;
        unsigned a[4];
        a[0] = totf(hw[gid * 20 + kl + t4]);
        a[1] = totf(hw[(gid + 8) * 20 + kl + t4]);
        a[2] = totf(hw[gid * 20 + kl + t4 + 4]);
        a[3] = totf(hw[(gid + 8) * 20 + kl + t4 + 4]);
        mma_tf32(e0, a, wgb[s][0][0], wgb[s][0][1]);
        mma_tf32(e1, a, wgb[s][1][0], wgb[s][1][1]);
    }

    // store hg (no dinv yet — counts not final until kernel end)
    int n0 = base + gid, n1 = n0 + 8;
    float2 st;
    st.x = e0[0]; st.y = e0[1];
    *(float2*)(g_hg + (long long)n0 * HID + 2 * t4) = st;
    st.x = e1[0]; st.y = e1[1];
    *(float2*)(g_hg + (long long)n0 * HID + 2 * t4 + 8) = st;
    st.x = e0[2]; st.y = e0[3];
    *(float2*)(g_hg + (long long)n1 * HID + 2 * t4) = st;
    st.x = e1[2]; st.y = e1[3];
    *(float2*)(g_hg + (long long)n1 * HID + 2 * t4 + 8) = st;
}

// ---------- hs = hg * rsqrt(deg)  (1 float4/thread; measured 5.6us) ----------
__global__ __launch_bounds__(256) void k_dinv() {
    int i = blockIdx.x * 256 + threadIdx.x;
    if (i >= N_NODES * 4) return;
    int node = i >> 2, q = i & 3;
    float dv = rsqrtf((float)(__ldg(&g_cnt[node]) + 1));
    float4 v = __ldg((const float4*)(g_hg + (long long)node * HID) + q);
    v.x *= dv; v.y *= dv; v.z *= dv; v.w *= dv;
    *((float4*)(g_hs + (long long)node * HID) + q) = v;
}

// ---------- fused gather + final (r14: predicated unrolled gather, sW2 stride 17) ----------
__global__ __launch_bounds__(256) void k_gather_final(
    const float* __restrict__ W2,
    const float* __restrict__ b2,
    const float* __restrict__ bg,
    float* __restrict__ out)
{
    __shared__ float sW2[N_CLASSES * 17];
    __shared__ float sb2[N_CLASSES];
    __shared__ float sbg[HID];
    int tid = threadIdx.x;
    for (int i = tid; i < N_CLASSES * HID; i += 256)
        sW2[(i >> 4) * 17 + (i & 15)] = W2[i];
    if (tid < N_CLASSES) sb2[tid] = b2[tid];
    if (tid < HID) sbg[tid] = bg[tid];
    __syncthreads();

    int warp = (blockIdx.x * 256 + tid) >> 5;
    if (warp >= N_NODES) return;
    int lane = tid & 31;
    int g = lane >> 2;
    int f = lane & 3;

    int cnt = __ldg(&g_cnt[warp]);
    int m = cnt < CAP ? cnt : CAP;
    const int* slots = g_slots + warp * CAP;

    int s0 = 0, s1 = 0;
    if (lane < m)      s0 = __ldg(slots + lane);
    if (32 + lane < m) s1 = __ldg(slots + 32 + lane);

    float ax = 0.f, ay = 0.f, az = 0.f, aw = 0.f;
    #pragma unroll
    for (int e = 0; e < 64; e += 8) {
        int idx = e + g;
        int sv = (e < 32) ? __shfl_sync(0xFFFFFFFFu, s0, idx)
                          : __shfl_sync(0xFFFFFFFFu, s1, idx - 32);
        if (idx < m) {
            float4 v = __ldg((const float4*)(g_hs + (long long)sv * HID) + f);
            ax += v.x; ay += v.y; az += v.z; aw += v.w;
        }
    }
    for (int e = 64; e < m; e += 8) {   // rare tail (deg > 64)
        int idx = e + g;
        if (idx < m) {
            int sv = __ldg(slots + idx);
            float4 v = __ldg((const float4*)(g_hs + (long long)sv * HID) + f);
            ax += v.x; ay += v.y; az += v.z; aw += v.w;
        }
    }
    #pragma unroll
    for (int off = 4; off < 32; off <<= 1) {
        ax += __shfl_xor_sync(0xFFFFFFFFu, ax, off);
        ay += __shfl_xor_sync(0xFFFFFFFFu, ay, off);
        az += __shfl_xor_sync(0xFFFFFFFFu, az, off);
        aw += __shfl_xor_sync(0xFFFFFFFFu, aw, off);
    }

    float4 self = __ldg((const float4*)(g_hs + (long long)warp * HID) + f);
    float dv = rsqrtf((float)(cnt + 1));
    float hp[4];
    {
        float t0 = (ax + self.x) * dv + sbg[4 * f + 0];
        float t1 = (ay + self.y) * dv + sbg[4 * f + 1];
        float t2 = (az + self.z) * dv + sbg[4 * f + 2];
        float t3 = (aw + self.w) * dv + sbg[4 * f + 3];
        hp[0] = t0 > 0.f ? t0 : 0.f;
        hp[1] = t1 > 0.f ? t1 : 0.f;
        hp[2] = t2 > 0.f ? t2 : 0.f;
        hp[3] = t3 > 0.f ? t3 : 0.f;
    }

    float h[HID];
    #pragma unroll
    for (int a = 0; a < 4; a++) {
        #pragma unroll
        for (int b = 0; b < 4; b++)
            h[a * 4 + b] = __shfl_sync(0xFFFFFFFFu, hp[b], a);
    }

    float l1 = sb2[lane];
    #pragma unroll
    for (int j = 0; j < HID; j++) l1 += h[j] * sW2[lane * 17 + j];
    float l2 = -3.4e38f;
    if (lane < N_CLASSES - 32) {
        l2 = sb2[32 + lane];
        #pragma unroll
        for (int j = 0; j < HID; j++) l2 += h[j] * sW2[(32 + lane) * 17 + j];
    }

    float mx = fmaxf(l1, l2);
    #pragma unroll
    for (int off = 16; off >= 1; off >>= 1)
        mx = fmaxf(mx, __shfl_xor_sync(0xFFFFFFFFu, mx, off));
    float ee = __expf(l1 - mx) + (lane < N_CLASSES - 32 ? __expf(l2 - mx) : 0.f);
    #pragma unroll
    for (int off = 16; off >= 1; off >>= 1)
        ee += __shfl_xor_sync(0xFFFFFFFFu, ee, off);
    float lse = __logf(ee) + mx;

    float* o = out + (long long)warp * N_CLASSES;
    o[lane] = l1 - lse;
    if (lane < N_CLASSES - 32) o[32 + lane] = l2 - lse;
}

extern "C" void kernel_launch(void* const* d_in, const int* in_sizes, int n_in,
                              void* d_out, int out_size) {
    const float* x  = (const float*)d_in[0];
    const void*  e  = d_in[1];
    const float* W1 = (const float*)d_in[2];
    const float* b1 = (const float*)d_in[3];
    const float* Wg = (const float*)d_in[4];
    const float* bg = (const float*)d_in[5];
    const float* W2 = (const float*)d_in[6];
    const float* b2 = (const float*)d_in[7];
    float* out = (float*)d_out;

    const int NB_N = (N_NODES + 255) / 256;
    const int NB_D = (N_NODES * 4 + 255) / 256;
    const int NB_G = (N_NODES * 32 + 255) / 256;

    cudaFuncSetAttribute(k_gemm_fill, cudaFuncAttributeMaxDynamicSharedMemorySize, SMEM_BYTES);

    k_prep<<<NB_N, 256>>>(e);
    k_gemm_fill<<<GB_GEMM, 256, SMEM_BYTES>>>((const float4*)x, W1, b1, Wg, e);
    k_dinv<<<NB_D, 256>>>();
    k_gather_final<<<NB_G, 256>>>(W2, b2, bg, out);
}

// round 16
// speedup vs baseline: 1.0366x; 1.0366x over previous
#include <cuda_runtime.h>
#include <cstdint>

#define N_NODES 100000
#define N_EDGES 3200000
#define F_IN    512
#define HID     16
#define N_CLASSES 40
#define CAP     128   // per-node in-edge bucket capacity

#define WARPS_PB 8
#define N_TILES  6250     // N_NODES / 16 (exact)
#define NB_HALF  782      // gemm blocks = fill blocks = 782; grid = 1564
#define E_PER_FB 4096     // edges per fill block (256 thr * 16)

// dynamic smem (floats): W1 interleaved [512][8] float2 = 8192; per-warp x tile [16][68]
#define SMEM_FLOATS (8192 + WARPS_PB * 1088)   // 16896 floats = 67584 B
#define SMEM_BYTES  (SMEM_FLOATS * 4)

// Scratch (device globals: allocation-free)
__device__ float g_hg[N_NODES * HID];      // hg = relu(x@W1^T+b1)@Wg^T
__device__ float g_hs[N_NODES * HID];      // hs = hg * rsqrt(deg)
__device__ int   g_cnt[N_NODES];
__device__ int   g_slots[N_NODES * CAP];
__device__ int   g_is64;

__device__ __forceinline__ unsigned totf(float x) {
    unsigned r;
    asm("cvt.rna.tf32.f32 %0, %1;" : "=r"(r) : "f"(x));
    return r;
}
__device__ __forceinline__ void mma_tf32(float* d, const unsigned* a, unsigned b0, unsigned b1) {
    asm volatile(
        "mma.sync.aligned.m16n8k8.row.col.f32.tf32.tf32.f32 "
        "{%0,%1,%2,%3}, {%4,%5,%6,%7}, {%8,%9}, {%0,%1,%2,%3};"
        : "+f"(d[0]), "+f"(d[1]), "+f"(d[2]), "+f"(d[3])
        : "r"(a[0]), "r"(a[1]), "r"(a[2]), "r"(a[3]), "r"(b0), "r"(b1));
}

// ---------- prep: zero counters + dtype detect ----------
__global__ __launch_bounds__(256) void k_prep(const void* e) {
    int i = blockIdx.x * 256 + threadIdx.x;
    if (i < N_NODES) g_cnt[i] = 0;
    if (blockIdx.x == 0 && threadIdx.x < 32) {
        const long long* p = (const long long*)e;
        long long v = p[(long long)threadIdx.x * (N_EDGES / 32)];   // max 24.8MB: in-bounds
        int ok = (v >= 0 && v < N_NODES) ? 1 : 0;
        unsigned m = __ballot_sync(0xFFFFFFFFu, ok);
        if (threadIdx.x == 0) g_is64 = (m == 0xFFFFFFFFu) ? 1 : 0;
    }
}

// ---------- fused: even blocks = r12 tf32 GEMM tile; odd blocks = CSR fill (MLP 16) ----------
// Block-level specialization: resources symmetric (one dynamic smem alloc, regs set by
// gemm branch), so occupancy is uniform. Gemm warps idle ~70% on DRAM latency; fill's
// LTS-atomic stream backfills those issue slots on the same SMs.
__global__ __launch_bounds__(256) void k_fused(
    const float4* __restrict__ x4,
    const float* __restrict__ W1,
    const float* __restrict__ b1,
    const float* __restrict__ Wg,
    const void* __restrict__ e)
{
    extern __shared__ float sm[];
    int tid = threadIdx.x;
    int vb = blockIdx.x;

    if (vb & 1) {
        // ================= fill branch: 16 edges/thread, batched atomics =================
        int fid = vb >> 1;
        long long be = (long long)fid * E_PER_FB + tid * 16;
        int is64 = g_is64;
        if (be + 16 <= N_EDGES) {
            int s[16], d[16], pos[16];
            if (is64) {
                const longlong4* ps = (const longlong4*)e + (be >> 2);
                const longlong4* pd = (const longlong4*)((const long long*)e + N_EDGES) + (be >> 2);
                #pragma unroll
                for (int q = 0; q < 4; q++) {
                    longlong4 a = ps[q];
                    s[4 * q] = (int)a.x; s[4 * q + 1] = (int)a.y;
                    s[4 * q + 2] = (int)a.z; s[4 * q + 3] = (int)a.w;
                    longlong4 b = pd[q];
                    d[4 * q] = (int)b.x; d[4 * q + 1] = (int)b.y;
                    d[4 * q + 2] = (int)b.z; d[4 * q + 3] = (int)b.w;
                }
            } else {
                const int4* ps = (const int4*)e + (be >> 2);
                const int4* pd = (const int4*)((const int*)e + N_EDGES) + (be >> 2);
                #pragma unroll
                for (int q = 0; q < 4; q++) {
                    int4 a = ps[q];
                    s[4 * q] = a.x; s[4 * q + 1] = a.y; s[4 * q + 2] = a.z; s[4 * q + 3] = a.w;
                    int4 b = pd[q];
                    d[4 * q] = b.x; d[4 * q + 1] = b.y; d[4 * q + 2] = b.z; d[4 * q + 3] = b.w;
                }
            }
            #pragma unroll
            for (int k = 0; k < 16; k++) pos[k] = atomicAdd(&g_cnt[d[k]], 1);
            #pragma unroll
            for (int k = 0; k < 16; k++)
                if (pos[k] < CAP) g_slots[d[k] * CAP + pos[k]] = s[k];
        } else {
            // tail (last fill block only)
            for (int k = 0; k < 16; k++) {
                long long ei = be + k;
                if (ei < N_EDGES) {
                    int es, ed;
                    if (is64) {
                        es = (int)((const long long*)e)[ei];
                        ed = (int)((const long long*)e)[N_EDGES + ei];
                    } else {
                        es = ((const int*)e)[ei];
                        ed = ((const int*)e)[N_EDGES + ei];
                    }
                    int pos = atomicAdd(&g_cnt[ed], 1);
                    if (pos < CAP) g_slots[ed * CAP + pos] = es;
                }
            }
        }
        return;
    }

    // ================= gemm branch: exact r12 body (65.2us measured) =================
    float2* w1i = (float2*)sm;
    for (int idx = tid; idx < 4096; idx += 256) {
        int k = idx >> 3, g = idx & 7;
        float2 v;
        v.x = __uint_as_float(totf(W1[g * F_IN + k]));
        v.y = __uint_as_float(totf(W1[(g + 8) * F_IN + k]));
        w1i[idx] = v;
    }
    __syncthreads();

    int wid = tid >> 5, lane = tid & 31;
    int gid = lane >> 2, t4 = lane & 3;
    int tile = (vb >> 1) * WARPS_PB + wid;
    if (tile >= N_TILES) return;
    int base = tile * 16;

    float* xw = sm + 8192 + wid * 1088;    // [16][68]
    float* hw = xw;                        // h1 tile [16][20] aliased after mainloop

    unsigned wgb[2][2][2];
    #pragma unroll
    for (int s = 0; s < 2; s++)
        #pragma unroll
        for (int h = 0; h < 2; h++) {
            wgb[s][h][0] = totf(__ldg(&Wg[(gid + 8 * h) * HID + t4 + 8 * s]));
            wgb[s][h][1] = totf(__ldg(&Wg[(gid + 8 * h) * HID + t4 + 4 + 8 * s]));
        }
    float bb0 = __ldg(&b1[2 * t4]);
    float bb1 = __ldg(&b1[2 * t4 + 1]);
    float bb2 = __ldg(&b1[2 * t4 + 8]);
    float bb3 = __ldg(&b1[2 * t4 + 9]);

    float d0[4] = {0.f, 0.f, 0.f, 0.f};
    float d1[4] = {0.f, 0.f, 0.f, 0.f};

    int c4 = lane & 15;
    int nrow = lane >> 4;

    float4 pf[8];
    #pragma unroll
    for (int p = 0; p < 8; p++)
        pf[p] = __ldg(x4 + (long long)(base + 2 * p + nrow) * (F_IN / 4) + c4);

    #pragma unroll 1
    for (int kc = 0; kc < 8; kc++) {
        #pragma unroll
        for (int p = 0; p < 8; p++) {
            float4 cv;
            cv.x = __uint_as_float(totf(pf[p].x));
            cv.y = __uint_as_float(totf(pf[p].y));
            cv.z = __uint_as_float(totf(pf[p].z));
            cv.w = __uint_as_float(totf(pf[p].w));
            ((float4*)(xw + (2 * p + nrow) * 68))[c4] = cv;
        }
        __syncwarp();
        if (kc < 7) {
            #pragma unroll
            for (int p = 0; p < 8; p++)
                pf[p] = __ldg(x4 + (long long)(base + 2 * p + nrow) * (F_IN / 4) + (kc + 1) * 16 + c4);
        }

        #pragma unroll
        for (int s = 0; s < 8; s++) {
            int kl = s * 8;
            unsigned a[4];
            a[0] = __float_as_uint(xw[gid * 68 + kl + t4]);
            a[1] = __float_as_uint(xw[(gid + 8) * 68 + kl + t4]);
            a[2] = __float_as_uint(xw[gid * 68 + kl + t4 + 4]);
            a[3] = __float_as_uint(xw[(gid + 8) * 68 + kl + t4 + 4]);
            int kg = kc * 64 + kl;
            float2 bA = w1i[(kg + t4) * 8 + gid];
            float2 bB = w1i[(kg + t4 + 4) * 8 + gid];
            mma_tf32(d0, a, __float_as_uint(bA.x), __float_as_uint(bB.x));
            mma_tf32(d1, a, __float_as_uint(bA.y), __float_as_uint(bB.y));
        }
        __syncwarp();
    }

    {
        float v;
        v = d0[0] + bb0; hw[gid * 20 + 2 * t4]           = v > 0.f ? v : 0.f;
        v = d0[1] + bb1; hw[gid * 20 + 2 * t4 + 1]       = v > 0.f ? v : 0.f;
        v = d0[2] + bb0; hw[(gid + 8) * 20 + 2 * t4]     = v > 0.f ? v : 0.f;
        v = d0[3] + bb1; hw[(gid + 8) * 20 + 2 * t4 + 1] = v > 0.f ? v : 0.f;
        v = d1[0] + bb2; hw[gid * 20 + 2 * t4 + 8]       = v > 0.f ? v : 0.f;
        v = d1[1] + bb3; hw[gid * 20 + 2 * t4 + 9]       = v > 0.f ? v : 0.f;
        v = d1[2] + bb2; hw[(gid + 8) * 20 + 2 * t4 + 8] = v > 0.f ? v : 0.f;
        v = d1[3] + bb3; hw[(gid + 8) * 20 + 2 * t4 + 9] = v > 0.f ? v : 0.f;
    }
    __syncwarp();

    float e0[4] = {0.f, 0.f, 0.f, 0.f};
    float e1[4] = {0.f, 0.f, 0.f, 0.f};
    #pragma unroll
    for (int s = 0; s < 2; s++) {
        int kl = s * 8;
        unsigned a[4];
        a[0] = totf(hw[gid * 20 + kl + t4]);
        a[1] = totf(hw[(gid + 8) * 20 + kl + t4]);
        a[2] = totf(hw[gid * 20 + kl + t4 + 4]);
        a[3] = totf(hw[(gid + 8) * 20 + kl + t4 + 4]);
        mma_tf32(e0, a, wgb[s][0][0], wgb[s][0][1]);
        mma_tf32(e1, a, wgb[s][1][0], wgb[s][1][1]);
    }

    // store hg (dinv applied by k_dinv after counts final)
    int n0 = base + gid, n1 = n0 + 8;
    float2 st;
    st.x = e0[0]; st.y = e0[1];
    *(float2*)(g_hg + (long long)n0 * HID + 2 * t4) = st;
    st.x = e1[0]; st.y = e1[1];
    *(float2*)(g_hg + (long long)n0 * HID + 2 * t4 + 8) = st;
    st.x = e0[2]; st.y = e0[3];
    *(float2*)(g_hg + (long long)n1 * HID + 2 * t4) = st;
    st.x = e1[2]; st.y = e1[3];
    *(float2*)(g_hg + (long long)n1 * HID + 2 * t4 + 8) = st;
}

// ---------- hs = hg * rsqrt(deg)  (1 float4/thread; measured 5.6us) ----------
__global__ __launch_bounds__(256) void k_dinv() {
    int i = blockIdx.x * 256 + threadIdx.x;
    if (i >= N_NODES * 4) return;
    int node = i >> 2, q = i & 3;
    float dv = rsqrtf((float)(__ldg(&g_cnt[node]) + 1));
    float4 v = __ldg((const float4*)(g_hg + (long long)node * HID) + q);
    v.x *= dv; v.y *= dv; v.z *= dv; v.w *= dv;
    *((float4*)(g_hs + (long long)node * HID) + q) = v;
}

// ---------- fused gather + final (r12 dynamic-loop version; sW2 stride 17) ----------
__global__ __launch_bounds__(256) void k_gather_final(
    const float* __restrict__ W2,
    const float* __restrict__ b2,
    const float* __restrict__ bg,
    float* __restrict__ out)
{
    __shared__ float sW2[N_CLASSES * 17];
    __shared__ float sb2[N_CLASSES];
    __shared__ float sbg[HID];
    int tid = threadIdx.x;
    for (int i = tid; i < N_CLASSES * HID; i += 256)
        sW2[(i >> 4) * 17 + (i & 15)] = W2[i];
    if (tid < N_CLASSES) sb2[tid] = b2[tid];
    if (tid < HID) sbg[tid] = bg[tid];
    __syncthreads();

    int warp = (blockIdx.x * 256 + tid) >> 5;
    if (warp >= N_NODES) return;
    int lane = tid & 31;
    int g = lane >> 2;
    int f = lane & 3;

    int cnt = __ldg(&g_cnt[warp]);
    int m = cnt < CAP ? cnt : CAP;
    const int* slots = g_slots + warp * CAP;

    int s0 = 0, s1 = 0;
    if (lane < m)      s0 = __ldg(slots + lane);
    if (32 + lane < m) s1 = __ldg(slots + 32 + lane);

    float ax = 0.f, ay = 0.f, az = 0.f, aw = 0.f;
    #pragma unroll 4
    for (int e = 0; e < m && e < 64; e += 8) {
        int idx = e + g;
        int sv = (e < 32) ? __shfl_sync(0xFFFFFFFFu, s0, idx)
                          : __shfl_sync(0xFFFFFFFFu, s1, idx - 32);
        if (idx < m) {
            float4 v = __ldg((const float4*)(g_hs + (long long)sv * HID) + f);
            ax += v.x; ay += v.y; az += v.z; aw += v.w;
        }
    }
    for (int e = 64; e < m; e += 8) {   // rare tail (deg > 64)
        int idx = e + g;
        if (idx < m) {
            int sv = __ldg(slots + idx);
            float4 v = __ldg((const float4*)(g_hs + (long long)sv * HID) + f);
            ax += v.x; ay += v.y; az += v.z; aw += v.w;
        }
    }
    #pragma unroll
    for (int off = 4; off < 32; off <<= 1) {
        ax += __shfl_xor_sync(0xFFFFFFFFu, ax, off);
        ay += __shfl_xor_sync(0xFFFFFFFFu, ay, off);
        az += __shfl_xor_sync(0xFFFFFFFFu, az, off);
        aw += __shfl_xor_sync(0xFFFFFFFFu, aw, off);
    }

    float4 self = __ldg((const float4*)(g_hs + (long long)warp * HID) + f);
    float dv = rsqrtf((float)(cnt + 1));
    float hp[4];
    {
        float t0 = (ax + self.x) * dv + sbg[4 * f + 0];
        float t1 = (ay + self.y) * dv + sbg[4 * f + 1];
        float t2 = (az + self.z) * dv + sbg[4 * f + 2];
        float t3 = (aw + self.w) * dv + sbg[4 * f + 3];
        hp[0] = t0 > 0.f ? t0 : 0.f;
        hp[1] = t1 > 0.f ? t1 : 0.f;
        hp[2] = t2 > 0.f ? t2 : 0.f;
        hp[3] = t3 > 0.f ? t3 : 0.f;
    }

    float h[HID];
    #pragma unroll
    for (int a = 0; a < 4; a++) {
        #pragma unroll
        for (int b = 0; b < 4; b++)
            h[a * 4 + b] = __shfl_sync(0xFFFFFFFFu, hp[b], a);
    }

    float l1 = sb2[lane];
    #pragma unroll
    for (int j = 0; j < HID; j++) l1 += h[j] * sW2[lane * 17 + j];
    float l2 = -3.4e38f;
    if (lane < N_CLASSES - 32) {
        l2 = sb2[32 + lane];
        #pragma unroll
        for (int j = 0; j < HID; j++) l2 += h[j] * sW2[(32 + lane) * 17 + j];
    }

    float mx = fmaxf(l1, l2);
    #pragma unroll
    for (int off = 16; off >= 1; off >>= 1)
        mx = fmaxf(mx, __shfl_xor_sync(0xFFFFFFFFu, mx, off));
    float ee = __expf(l1 - mx) + (lane < N_CLASSES - 32 ? __expf(l2 - mx) : 0.f);
    #pragma unroll
    for (int off = 16; off >= 1; off >>= 1)
        ee += __shfl_xor_sync(0xFFFFFFFFu, ee, off);
    float lse = __logf(ee) + mx;

    float* o = out + (long long)warp * N_CLASSES;
    o[lane] = l1 - lse;
    if (lane < N_CLASSES - 32) o[32 + lane] = l2 - lse;
}

extern "C" void kernel_launch(void* const* d_in, const int* in_sizes, int n_in,
                              void* d_out, int out_size) {
    const float* x  = (const float*)d_in[0];
    const void*  e  = d_in[1];
    const float* W1 = (const float*)d_in[2];
    const float* b1 = (const float*)d_in[3];
    const float* Wg = (const float*)d_in[4];
    const float* bg = (const float*)d_in[5];
    const float* W2 = (const float*)d_in[6];
    const float* b2 = (const float*)d_in[7];
    float* out = (float*)d_out;

    const int NB_N = (N_NODES + 255) / 256;
    const int NB_D = (N_NODES * 4 + 255) / 256;
    const int NB_G = (N_NODES * 32 + 255) / 256;

    cudaFuncSetAttribute(k_fused, cudaFuncAttributeMaxDynamicSharedMemorySize, SMEM_BYTES);

    k_prep<<<NB_N, 256>>>(e);                                            // launch 1
    k_fused<<<NB_HALF * 2, 256, SMEM_BYTES>>>((const float4*)x, W1, b1, Wg, e); // launch 2
    k_dinv<<<NB_D, 256>>>();                                             // launch 3
    k_gather_final<<<NB_G, 256>>>(W2, b2, bg, out);                      // launch 4 (profiled)
}

// round 17
// speedup vs baseline: 1.1534x; 1.1126x over previous
#include <cuda_runtime.h>
#include <cstdint>

#define N_NODES 100000
#define N_EDGES 3200000
#define F_IN    512
#define HID     16
#define N_CLASSES 40
#define CAP     128   // per-node in-edge bucket capacity

#define WARPS_PB 8
#define N_TILES  6250     // N_NODES / 16 (exact)
#define GB_GEMM  782      // ceil(6250 / 8)

// dynamic smem (floats): W1 interleaved [512][8] float2 = 8192; per-warp x tile [16][68]
#define SMEM_FLOATS (8192 + WARPS_PB * 1088)   // 16896 floats = 67584 B
#define SMEM_BYTES  (SMEM_FLOATS * 4)

// Scratch (device globals: allocation-free)
__device__ float g_hs[N_NODES * HID];      // hs = relu(x@W1^T+b1)@Wg^T * rsqrt(deg)
__device__ float g_out[N_NODES * HID];     // gcn output pre-bias
__device__ int   g_cnt[N_NODES];
__device__ int   g_slots[N_NODES * CAP];
__device__ int   g_is64;

__device__ __forceinline__ unsigned totf(float x) {
    unsigned r;
    asm("cvt.rna.tf32.f32 %0, %1;" : "=r"(r) : "f"(x));
    return r;
}
__device__ __forceinline__ void mma_tf32(float* d, const unsigned* a, unsigned b0, unsigned b1) {
    asm volatile(
        "mma.sync.aligned.m16n8k8.row.col.f32.tf32.tf32.f32 "
        "{%0,%1,%2,%3}, {%4,%5,%6,%7}, {%8,%9}, {%0,%1,%2,%3};"
        : "+f"(d[0]), "+f"(d[1]), "+f"(d[2]), "+f"(d[3])
        : "r"(a[0]), "r"(a[1]), "r"(a[2]), "r"(a[3]), "r"(b0), "r"(b1));
}

// ---------- prep: zero counters + dtype detect ----------
__global__ __launch_bounds__(256) void k_prep(const void* e) {
    int i = blockIdx.x * 256 + threadIdx.x;
    if (i < N_NODES) g_cnt[i] = 0;
    if (blockIdx.x == 0 && threadIdx.x < 32) {
        const long long* p = (const long long*)e;
        long long v = p[(long long)threadIdx.x * (N_EDGES / 32)];   // max 24.8MB: in-bounds
        int ok = (v >= 0 && v < N_NODES) ? 1 : 0;
        unsigned m = __ballot_sync(0xFFFFFFFFu, ok);
        if (threadIdx.x == 0) g_is64 = (m == 0xFFFFFFFFu) ? 1 : 0;
    }
}

// ---------- fill bucketed CSR: 4 edges/thread (r12 known-good, 46us) ----------
__global__ __launch_bounds__(256) void k_fill(const void* __restrict__ e) {
    int t = blockIdx.x * 256 + threadIdx.x;
    if (t >= N_EDGES / 4) return;
    int s[4], d[4];
    if (g_is64) {
        const longlong4* ps = (const longlong4*)e;
        const longlong4* pd = (const longlong4*)((const long long*)e + N_EDGES);
        longlong4 a = ps[t];
        longlong4 b = pd[t];
        s[0] = (int)a.x; s[1] = (int)a.y; s[2] = (int)a.z; s[3] = (int)a.w;
        d[0] = (int)b.x; d[1] = (int)b.y; d[2] = (int)b.z; d[3] = (int)b.w;
    } else {
        const int4* ps = (const int4*)e;
        const int4* pd = (const int4*)((const int*)e + N_EDGES);
        int4 a = ps[t];
        int4 b = pd[t];
        s[0] = a.x; s[1] = a.y; s[2] = a.z; s[3] = a.w;
        d[0] = b.x; d[1] = b.y; d[2] = b.z; d[3] = b.w;
    }
    int pos[4];
    #pragma unroll
    for (int k = 0; k < 4; k++) pos[k] = atomicAdd(&g_cnt[d[k]], 1);
    #pragma unroll
    for (int k = 0; k < 4; k++)
        if (pos[k] < CAP) g_slots[d[k] * CAP + pos[k]] = s[k];
}

// ---------- K0 via tf32 mma.sync, software-pipelined LDG (r12 known-good, 65.2us) ----------
__global__ __launch_bounds__(256) void k_gemm1(
    const float4* __restrict__ x4,
    const float* __restrict__ W1,
    const float* __restrict__ b1,
    const float* __restrict__ Wg)
{
    extern __shared__ float sm[];
    float2* w1i = (float2*)sm;

    int tid = threadIdx.x;
    for (int idx = tid; idx < 4096; idx += 256) {
        int k = idx >> 3, g = idx & 7;
        float2 v;
        v.x = __uint_as_float(totf(W1[g * F_IN + k]));
        v.y = __uint_as_float(totf(W1[(g + 8) * F_IN + k]));
        w1i[idx] = v;
    }
    __syncthreads();

    int wid = tid >> 5, lane = tid & 31;
    int gid = lane >> 2, t4 = lane & 3;
    int tile = blockIdx.x * WARPS_PB + wid;
    if (tile >= N_TILES) return;
    int base = tile * 16;

    float* xw = sm + 8192 + wid * 1088;    // [16][68]
    float* hw = xw;                        // h1 tile [16][20] aliased after mainloop

    unsigned wgb[2][2][2];
    #pragma unroll
    for (int s = 0; s < 2; s++)
        #pragma unroll
        for (int h = 0; h < 2; h++) {
            wgb[s][h][0] = totf(__ldg(&Wg[(gid + 8 * h) * HID + t4 + 8 * s]));
            wgb[s][h][1] = totf(__ldg(&Wg[(gid + 8 * h) * HID + t4 + 4 + 8 * s]));
        }
    float bb0 = __ldg(&b1[2 * t4]);
    float bb1 = __ldg(&b1[2 * t4 + 1]);
    float bb2 = __ldg(&b1[2 * t4 + 8]);
    float bb3 = __ldg(&b1[2 * t4 + 9]);

    float d0[4] = {0.f, 0.f, 0.f, 0.f};
    float d1[4] = {0.f, 0.f, 0.f, 0.f};

    int c4 = lane & 15;
    int nrow = lane >> 4;

    float4 pf[8];
    #pragma unroll
    for (int p = 0; p < 8; p++)
        pf[p] = __ldg(x4 + (long long)(base + 2 * p + nrow) * (F_IN / 4) + c4);

    #pragma unroll 1
    for (int kc = 0; kc < 8; kc++) {
        #pragma unroll
        for (int p = 0; p < 8; p++) {
            float4 cv;
            cv.x = __uint_as_float(totf(pf[p].x));
            cv.y = __uint_as_float(totf(pf[p].y));
            cv.z = __uint_as_float(totf(pf[p].z));
            cv.w = __uint_as_float(totf(pf[p].w));
            ((float4*)(xw + (2 * p + nrow) * 68))[c4] = cv;
        }
        __syncwarp();
        if (kc < 7) {
            #pragma unroll
            for (int p = 0; p < 8; p++)
                pf[p] = __ldg(x4 + (long long)(base + 2 * p + nrow) * (F_IN / 4) + (kc + 1) * 16 + c4);
        }

        #pragma unroll
        for (int s = 0; s < 8; s++) {
            int kl = s * 8;
            unsigned a[4];
            a[0] = __float_as_uint(xw[gid * 68 + kl + t4]);
            a[1] = __float_as_uint(xw[(gid + 8) * 68 + kl + t4]);
            a[2] = __float_as_uint(xw[gid * 68 + kl + t4 + 4]);
            a[3] = __float_as_uint(xw[(gid + 8) * 68 + kl + t4 + 4]);
            int kg = kc * 64 + kl;
            float2 bA = w1i[(kg + t4) * 8 + gid];
            float2 bB = w1i[(kg + t4 + 4) * 8 + gid];
            mma_tf32(d0, a, __float_as_uint(bA.x), __float_as_uint(bB.x));
            mma_tf32(d1, a, __float_as_uint(bA.y), __float_as_uint(bB.y));
        }
        __syncwarp();
    }

    {
        float v;
        v = d0[0] + bb0; hw[gid * 20 + 2 * t4]           = v > 0.f ? v : 0.f;
        v = d0[1] + bb1; hw[gid * 20 + 2 * t4 + 1]       = v > 0.f ? v : 0.f;
        v = d0[2] + bb0; hw[(gid + 8) * 20 + 2 * t4]     = v > 0.f ? v : 0.f;
        v = d0[3] + bb1; hw[(gid + 8) * 20 + 2 * t4 + 1] = v > 0.f ? v : 0.f;
        v = d1[0] + bb2; hw[gid * 20 + 2 * t4 + 8]       = v > 0.f ? v : 0.f;
        v = d1[1] + bb3; hw[gid * 20 + 2 * t4 + 9]       = v > 0.f ? v : 0.f;
        v = d1[2] + bb2; hw[(gid + 8) * 20 + 2 * t4 + 8] = v > 0.f ? v : 0.f;
        v = d1[3] + bb3; hw[(gid + 8) * 20 + 2 * t4 + 9] = v > 0.f ? v : 0.f;
    }
    __syncwarp();

    float e0[4] = {0.f, 0.f, 0.f, 0.f};
    float e1[4] = {0.f, 0.f, 0.f, 0.f};
    #pragma unroll
    for (int s = 0; s < 2; s++) {
        int kl = s * 8;
        unsigned a[4];
        a[0] = totf(hw[gid * 20 + kl + t4]);
        a[1] = totf(hw[(gid + 8) * 20 + kl + t4]);
        a[2] = totf(hw[gid * 20 + kl + t4 + 4]);
        a[3] = totf(hw[(gid + 8) * 20 + kl + t4 + 4]);
        mma_tf32(e0, a, wgb[s][0][0], wgb[s][0][1]);
        mma_tf32(e1, a, wgb[s][1][0], wgb[s][1][1]);
    }

    // dinv fused: counts are final (fill runs before gemm)
    int n0 = base + gid, n1 = n0 + 8;
    float dv0 = rsqrtf((float)(__ldg(&g_cnt[n0]) + 1));
    float dv1 = rsqrtf((float)(__ldg(&g_cnt[n1]) + 1));
    float2 st;
    st.x = e0[0] * dv0; st.y = e0[1] * dv0;
    *(float2*)(g_hs + (long long)n0 * HID + 2 * t4) = st;
    st.x = e1[0] * dv0; st.y = e1[1] * dv0;
    *(float2*)(g_hs + (long long)n0 * HID + 2 * t4 + 8) = st;
    st.x = e0[2] * dv1; st.y = e0[3] * dv1;
    *(float2*)(g_hs + (long long)n1 * HID + 2 * t4) = st;
    st.x = e1[2] * dv1; st.y = e1[3] * dv1;
    *(float2*)(g_hs + (long long)n1 * HID + 2 * t4 + 8) = st;
}

// ---------- gather only (r6 shape, measured 34.4us): g_out = (sum + self) * dinv ----------
__global__ __launch_bounds__(256) void k_gather() {
    int warp = (blockIdx.x * 256 + threadIdx.x) >> 5;
    if (warp >= N_NODES) return;
    int lane = threadIdx.x & 31;
    int g = lane >> 2;        // edge group 0..7
    int f = lane & 3;         // float4 index 0..3

    int cnt = __ldg(&g_cnt[warp]);
    int m = cnt < CAP ? cnt : CAP;
    const int* slots = g_slots + warp * CAP;

    int s0 = 0, s1 = 0;
    if (lane < m)      s0 = __ldg(slots + lane);
    if (32 + lane < m) s1 = __ldg(slots + 32 + lane);

    float ax = 0.f, ay = 0.f, az = 0.f, aw = 0.f;
    #pragma unroll 4
    for (int e = 0; e < m && e < 64; e += 8) {
        int idx = e + g;
        int sv = (e < 32) ? __shfl_sync(0xFFFFFFFFu, s0, idx)
                          : __shfl_sync(0xFFFFFFFFu, s1, idx - 32);
        if (idx < m) {
            float4 v = __ldg((const float4*)(g_hs + (long long)sv * HID) + f);
            ax += v.x; ay += v.y; az += v.z; aw += v.w;
        }
    }
    for (int e = 64; e < m; e += 8) {   // rare tail (deg > 64)
        int idx = e + g;
        if (idx < m) {
            int sv = __ldg(slots + idx);
            float4 v = __ldg((const float4*)(g_hs + (long long)sv * HID) + f);
            ax += v.x; ay += v.y; az += v.z; aw += v.w;
        }
    }
    #pragma unroll
    for (int off = 4; off < 32; off <<= 1) {
        ax += __shfl_xor_sync(0xFFFFFFFFu, ax, off);
        ay += __shfl_xor_sync(0xFFFFFFFFu, ay, off);
        az += __shfl_xor_sync(0xFFFFFFFFu, az, off);
        aw += __shfl_xor_sync(0xFFFFFFFFu, aw, off);
    }

    if (g == 0) {
        float4 self = __ldg((const float4*)(g_hs + (long long)warp * HID) + f);
        float dv = rsqrtf((float)(cnt + 1));
        float4 o = make_float4((ax + self.x) * dv, (ay + self.y) * dv,
                               (az + self.z) * dv, (aw + self.w) * dv);
        *((float4*)(g_out + (long long)warp * HID) + f) = o;
    }
}

// ---------- final (r3 shape, measured ~8us): thread-per-node logits + log_softmax ----------
__global__ __launch_bounds__(256) void k_final(
    const float* __restrict__ W2,
    const float* __restrict__ b2,
    const float* __restrict__ bg,
    float* __restrict__ out)
{
    __shared__ float sW2[N_CLASSES * HID];
    __shared__ float sb2[N_CLASSES];
    __shared__ float sbg[HID];
    int tid = threadIdx.x;
    for (int idx = tid; idx < N_CLASSES * HID; idx += 256) sW2[idx] = W2[idx];
    if (tid < N_CLASSES) sb2[tid] = b2[tid];
    if (tid < HID) sbg[tid] = bg[tid];
    __syncthreads();

    int i = blockIdx.x * 256 + tid;
    if (i >= N_NODES) return;

    float h[HID];
    const float4* a = (const float4*)(g_out + (long long)i * HID);
    #pragma unroll
    for (int q = 0; q < 4; q++) {
        float4 v = a[q];
        float v0 = v.x + sbg[4 * q + 0];
        float v1 = v.y + sbg[4 * q + 1];
        float v2 = v.z + sbg[4 * q + 2];
        float v3 = v.w + sbg[4 * q + 3];
        h[4 * q + 0] = v0 > 0.f ? v0 : 0.f;
        h[4 * q + 1] = v1 > 0.f ? v1 : 0.f;
        h[4 * q + 2] = v2 > 0.f ? v2 : 0.f;
        h[4 * q + 3] = v3 > 0.f ? v3 : 0.f;
    }

    float lg[N_CLASSES];
    float mx = -3.4e38f;
    #pragma unroll
    for (int c = 0; c < N_CLASSES; c++) {
        float s = sb2[c];
        #pragma unroll
        for (int j = 0; j < HID; j++) s += h[j] * sW2[c * HID + j];  // broadcast LDS
        lg[c] = s;
        mx = fmaxf(mx, s);
    }
    float se = 0.f;
    #pragma unroll
    for (int c = 0; c < N_CLASSES; c++) se += __expf(lg[c] - mx);
    float lse = __logf(se) + mx;

    float* o = out + (long long)i * N_CLASSES;
    #pragma unroll
    for (int c4 = 0; c4 < N_CLASSES / 4; c4++) {
        ((float4*)o)[c4] = make_float4(lg[4 * c4 + 0] - lse, lg[4 * c4 + 1] - lse,
                                       lg[4 * c4 + 2] - lse, lg[4 * c4 + 3] - lse);
    }
}

extern "C" void kernel_launch(void* const* d_in, const int* in_sizes, int n_in,
                              void* d_out, int out_size) {
    const float* x  = (const float*)d_in[0];
    const void*  e  = d_in[1];
    const float* W1 = (const float*)d_in[2];
    const float* b1 = (const float*)d_in[3];
    const float* Wg = (const float*)d_in[4];
    const float* bg = (const float*)d_in[5];
    const float* W2 = (const float*)d_in[6];
    const float* b2 = (const float*)d_in[7];
    float* out = (float*)d_out;

    const int NB_N  = (N_NODES + 255) / 256;
    const int NB_E4 = (N_EDGES / 4 + 255) / 256;
    const int NB_G  = (N_NODES * 32 + 255) / 256;

    cudaFuncSetAttribute(k_gemm1, cudaFuncAttributeMaxDynamicSharedMemorySize, SMEM_BYTES);

    k_prep<<<NB_N, 256>>>(e);                                            // launch 1
    k_fill<<<NB_E4, 256>>>(e);                                           // launch 2
    k_gemm1<<<GB_GEMM, 256, SMEM_BYTES>>>((const float4*)x, W1, b1, Wg); // launch 3
    k_gather<<<NB_G, 256>>>();                                           // launch 4 (profiled)
    k_final<<<NB_N, 256>>>(W2, b2, bg, out);                             // launch 5
}